// round 1
// baseline (speedup 1.0000x reference)
#include <cuda_runtime.h>
#include <math_constants.h>
#include <math.h>

#define B_ 8
#define T_ 2048
#define C_ 1024
#define H_ 64
#define M_ (B_*T_)

// Scratch for projected q/k/v (real & imag). 6 * 4MB = 24MB static device memory.
__device__ float g_qr[M_*H_];
__device__ float g_qi[M_*H_];
__device__ float g_kr[M_*H_];
__device__ float g_ki[M_*H_];
__device__ float g_vr[M_*H_];
__device__ float g_vi[M_*H_];

// ---------------------------------------------------------------------------
// Projection kernel: computes q,k,v (complex) = (xr + i xi) @ (Wr + i Wi)
// Tile: 32 rows per block, all 64 head dims, all 6 outputs fused so x is
// read once. x tile staged in smem (warp-broadcast reads); W read through
// coalesced LDG (L2-resident, shared by all 512 blocks).
// ---------------------------------------------------------------------------
__global__ __launch_bounds__(256) void proj_kernel(
    const float* __restrict__ xr,  const float* __restrict__ xi,
    const float* __restrict__ Wkr, const float* __restrict__ Wki,
    const float* __restrict__ Wqr, const float* __restrict__ Wqi,
    const float* __restrict__ Wvr, const float* __restrict__ Wvi)
{
    __shared__ float sxr[32][32];
    __shared__ float sxi[32][32];

    const int tid = threadIdx.x;
    const int h   = tid & 63;        // head dim this thread owns
    const int rg  = tid >> 6;        // row group 0..3 (8 rows each)
    const int m0  = blockIdx.x * 32;

    float akr[8], aki[8], aqr[8], aqi[8], avr[8], avi[8];
    #pragma unroll
    for (int r = 0; r < 8; ++r) {
        akr[r]=0.f; aki[r]=0.f; aqr[r]=0.f; aqi[r]=0.f; avr[r]=0.f; avi[r]=0.f;
    }

    for (int c0 = 0; c0 < C_; c0 += 32) {
        __syncthreads();
        #pragma unroll
        for (int i = tid; i < 32*32; i += 256) {
            int r = i >> 5, c = i & 31;
            sxr[r][c] = xr[(size_t)(m0 + r)*C_ + c0 + c];
            sxi[r][c] = xi[(size_t)(m0 + r)*C_ + c0 + c];
        }
        __syncthreads();

        #pragma unroll 4
        for (int c = 0; c < 32; ++c) {
            const int wofs = (c0 + c)*H_ + h;
            const float wkr = Wkr[wofs], wki = Wki[wofs];
            const float wqr = Wqr[wofs], wqi = Wqi[wofs];
            const float wvr = Wvr[wofs], wvi = Wvi[wofs];
            #pragma unroll
            for (int r = 0; r < 8; ++r) {
                const float ar = sxr[rg*8 + r][c];
                const float ai = sxi[rg*8 + r][c];
                akr[r] = fmaf(ar, wkr, akr[r]); akr[r] = fmaf(-ai, wki, akr[r]);
                aki[r] = fmaf(ai, wkr, aki[r]); aki[r] = fmaf( ar, wki, aki[r]);
                aqr[r] = fmaf(ar, wqr, aqr[r]); aqr[r] = fmaf(-ai, wqi, aqr[r]);
                aqi[r] = fmaf(ai, wqr, aqi[r]); aqi[r] = fmaf( ar, wqi, aqi[r]);
                avr[r] = fmaf(ar, wvr, avr[r]); avr[r] = fmaf(-ai, wvi, avr[r]);
                avi[r] = fmaf(ai, wvr, avi[r]); avi[r] = fmaf( ar, wvi, avi[r]);
            }
        }
    }

    #pragma unroll
    for (int r = 0; r < 8; ++r) {
        const size_t o = (size_t)(m0 + rg*8 + r)*H_ + h;
        g_kr[o] = akr[r]; g_ki[o] = aki[r];
        g_qr[o] = aqr[r]; g_qi[o] = aqi[r];
        g_vr[o] = avr[r]; g_vi[o] = avi[r];
    }
}

// ---------------------------------------------------------------------------
// Flash-style complex attention.
// One block per (batch, 64-query tile). 256 threads as 16x16; each thread
// owns a 4x4 score tile and a 4x4 (q,h) output tile.
// Q/K stored [h][row] (transposed, stride 68) so score loop uses LDS.128.
// V stored [row][h] stride 68. P staged transposed [k][q] for the PV GEMM.
// ---------------------------------------------------------------------------
#define KST 68

struct AttnSmem {
    float Qr[64][KST];
    float Qi[64][KST];
    float Kr[64][KST];
    float Ki[64][KST];
    float Vr[64][KST];
    float Vi[64][KST];
    float P [64][KST];
    float M[64];
    float L[64];
};

__global__ __launch_bounds__(256) void attn_kernel(float* __restrict__ out)
{
    extern __shared__ char smem_raw[];
    AttnSmem& s = *reinterpret_cast<AttnSmem*>(smem_raw);

    const int b   = blockIdx.y;
    const int qt  = (int)gridDim.x - 1 - (int)blockIdx.x;  // heavy tiles first
    const int tid = threadIdx.x;
    const int tx  = tid & 15;
    const int ty  = tid >> 4;

    const int qbase = b*T_ + qt*64;

    // Load Q tile transposed: s.Q[h][row]
    for (int i = tid; i < 64*H_; i += 256) {
        int row = i >> 6, hh = i & 63;
        s.Qr[hh][row] = g_qr[(size_t)(qbase+row)*H_ + hh];
        s.Qi[hh][row] = g_qi[(size_t)(qbase+row)*H_ + hh];
    }
    if (tid < 64) { s.M[tid] = -CUDART_INF_F; s.L[tid] = 0.f; }

    float o_r[4][4], o_i[4][4];
    #pragma unroll
    for (int a=0;a<4;a++)
        #pragma unroll
        for (int c=0;c<4;c++) { o_r[a][c]=0.f; o_i[a][c]=0.f; }

    for (int kt = 0; kt <= qt; ++kt) {
        __syncthreads();   // protect s.K/s.V/s.P from previous iteration readers
        const int kbase = b*T_ + kt*64;
        for (int i = tid; i < 64*H_; i += 256) {
            int row = i >> 6, hh = i & 63;
            s.Kr[hh][row] = g_kr[(size_t)(kbase+row)*H_ + hh];
            s.Ki[hh][row] = g_ki[(size_t)(kbase+row)*H_ + hh];
            s.Vr[row][hh] = g_vr[(size_t)(kbase+row)*H_ + hh];
            s.Vi[row][hh] = g_vi[(size_t)(kbase+row)*H_ + hh];
        }
        __syncthreads();

        // --- complex scores over H ---
        float sr[4][4], si[4][4];
        #pragma unroll
        for (int a=0;a<4;a++)
            #pragma unroll
            for (int c=0;c<4;c++) { sr[a][c]=0.f; si[a][c]=0.f; }

        #pragma unroll 4
        for (int hh = 0; hh < H_; ++hh) {
            const float4 q4r = *(const float4*)&s.Qr[hh][ty*4];
            const float4 q4i = *(const float4*)&s.Qi[hh][ty*4];
            const float4 k4r = *(const float4*)&s.Kr[hh][tx*4];
            const float4 k4i = *(const float4*)&s.Ki[hh][tx*4];
            const float qra[4] = {q4r.x,q4r.y,q4r.z,q4r.w};
            const float qia[4] = {q4i.x,q4i.y,q4i.z,q4i.w};
            const float kra[4] = {k4r.x,k4r.y,k4r.z,k4r.w};
            const float kia[4] = {k4i.x,k4i.y,k4i.z,k4i.w};
            #pragma unroll
            for (int a=0;a<4;a++)
                #pragma unroll
                for (int c=0;c<4;c++) {
                    sr[a][c] = fmaf(qra[a], kra[c], sr[a][c]);
                    sr[a][c] = fmaf(qia[a], kia[c], sr[a][c]);
                    si[a][c] = fmaf(qia[a], kra[c], si[a][c]);
                    si[a][c] = fmaf(-qra[a], kia[c], si[a][c]);
                }
        }

        // --- magnitude + causal mask + row max ---
        float p[4][4];
        float rowmax[4];
        #pragma unroll
        for (int a=0;a<4;a++) rowmax[a] = -CUDART_INF_F;
        #pragma unroll
        for (int a=0;a<4;a++) {
            const int qg = qt*64 + ty*4 + a;
            #pragma unroll
            for (int c=0;c<4;c++) {
                const int kg = kt*64 + tx*4 + c;
                float v = sqrtf(fmaf(sr[a][c], sr[a][c],
                                fmaf(si[a][c], si[a][c], 1e-4f))) * 0.125f;
                v = (kg <= qg) ? v : -CUDART_INF_F;
                p[a][c] = v;
                rowmax[a] = fmaxf(rowmax[a], v);
            }
        }
        #pragma unroll
        for (int off = 8; off; off >>= 1)
            #pragma unroll
            for (int a=0;a<4;a++)
                rowmax[a] = fmaxf(rowmax[a],
                                  __shfl_xor_sync(0xffffffffu, rowmax[a], off));

        // --- online softmax stats ---
        float m_new[4], scale[4], rowsum[4];
        #pragma unroll
        for (int a=0;a<4;a++) {
            const float m_old = s.M[ty*4+a];
            m_new[a]  = fmaxf(m_old, rowmax[a]);
            scale[a]  = expf(m_old - m_new[a]);   // expf(-inf)=0 on first tile
            rowsum[a] = 0.f;
        }
        #pragma unroll
        for (int a=0;a<4;a++)
            #pragma unroll
            for (int c=0;c<4;c++) {
                const float e = expf(p[a][c] - m_new[a]);  // masked -> 0
                p[a][c] = e;
                rowsum[a] += e;
            }
        #pragma unroll
        for (int off = 8; off; off >>= 1)
            #pragma unroll
            for (int a=0;a<4;a++)
                rowsum[a] += __shfl_xor_sync(0xffffffffu, rowsum[a], off);

        __syncwarp();    // all lanes read s.M before the update below
        if (tx == 0) {
            #pragma unroll
            for (int a=0;a<4;a++) {
                s.M[ty*4+a] = m_new[a];
                s.L[ty*4+a] = s.L[ty*4+a]*scale[a] + rowsum[a];
            }
        }

        // rescale accumulators
        #pragma unroll
        for (int a=0;a<4;a++)
            #pragma unroll
            for (int c=0;c<4;c++) { o_r[a][c] *= scale[a]; o_i[a][c] *= scale[a]; }

        // stage P transposed [k][q]
        #pragma unroll
        for (int a=0;a<4;a++)
            #pragma unroll
            for (int c=0;c<4;c++)
                s.P[tx*4+c][ty*4+a] = p[a][c];
        __syncthreads();

        // --- O += P @ V ---
        #pragma unroll 4
        for (int kk = 0; kk < 64; ++kk) {
            const float4 p4  = *(const float4*)&s.P [kk][ty*4];
            const float4 v4r = *(const float4*)&s.Vr[kk][tx*4];
            const float4 v4i = *(const float4*)&s.Vi[kk][tx*4];
            const float pa [4] = {p4.x,p4.y,p4.z,p4.w};
            const float vra[4] = {v4r.x,v4r.y,v4r.z,v4r.w};
            const float via[4] = {v4i.x,v4i.y,v4i.z,v4i.w};
            #pragma unroll
            for (int a=0;a<4;a++)
                #pragma unroll
                for (int c=0;c<4;c++) {
                    o_r[a][c] = fmaf(pa[a], vra[c], o_r[a][c]);
                    o_i[a][c] = fmaf(pa[a], via[c], o_i[a][c]);
                }
        }
    }

    __syncthreads();
    float inv[4];
    #pragma unroll
    for (int a=0;a<4;a++) inv[a] = 1.f / s.L[ty*4+a];

    #pragma unroll
    for (int a=0;a<4;a++) {
        const size_t row = (size_t)(qbase + ty*4 + a);
        float4 vr, vi;
        vr.x = o_r[a][0]*inv[a]; vr.y = o_r[a][1]*inv[a];
        vr.z = o_r[a][2]*inv[a]; vr.w = o_r[a][3]*inv[a];
        vi.x = o_i[a][0]*inv[a]; vi.y = o_i[a][1]*inv[a];
        vi.z = o_i[a][2]*inv[a]; vi.w = o_i[a][3]*inv[a];
        *(float4*)&out[row*H_ + tx*4]                    = vr;   // out_real
        *(float4*)&out[(size_t)M_*H_ + row*H_ + tx*4]    = vi;   // out_imag
    }
}

// ---------------------------------------------------------------------------
extern "C" void kernel_launch(void* const* d_in, const int* in_sizes, int n_in,
                              void* d_out, int out_size)
{
    const float* xr  = (const float*)d_in[0];
    const float* xi  = (const float*)d_in[1];
    const float* Wkr = (const float*)d_in[2];
    const float* Wki = (const float*)d_in[3];
    const float* Wqr = (const float*)d_in[4];
    const float* Wqi = (const float*)d_in[5];
    const float* Wvr = (const float*)d_in[6];
    const float* Wvi = (const float*)d_in[7];

    cudaFuncSetAttribute(attn_kernel,
                         cudaFuncAttributeMaxDynamicSharedMemorySize,
                         (int)sizeof(AttnSmem));

    proj_kernel<<<M_/32, 256>>>(xr, xi, Wkr, Wki, Wqr, Wqi, Wvr, Wvi);

    dim3 ag(T_/64, B_);
    attn_kernel<<<ag, 256, sizeof(AttnSmem)>>>((float*)d_out);
}